// round 1
// baseline (speedup 1.0000x reference)
#include <cuda_runtime.h>
#include <math.h>

#define BB 2
#define SS 2048
#define DD 1024
#define HH 16
#define DK 64
#define MTOT (BB*SS)

#define SCALE 12.5f                  // 100/sqrt(64)
#define INV_HS (1.0f/32768.0f)       // 1/(H*S)

// ---------------- scratch (static device globals; no allocation) -------------
__device__ float g_Q[MTOT*DD];
__device__ float g_K[MTOT*DD];
__device__ float g_V[MTOT*DD];
__device__ float g_C[MTOT*DD];

// ---------------- zero mean_atp region ---------------------------------------
__global__ void zero_atp_kernel(float* __restrict__ atp) {
    int i = blockIdx.x * blockDim.x + threadIdx.x;
    if (i < BB*SS) atp[i] = 0.0f;
}

// ---------------- SGEMM: Y[M,N] = X[M,K] @ W[N,K]^T + bias[N] ----------------
// 128x128x16 tile, 256 threads, 8x8 microtile, transposed smem with pad.
__global__ __launch_bounds__(256) void sgemm_bias_xwT(
    const float* __restrict__ X, const float* __restrict__ W,
    const float* __restrict__ bias, float* __restrict__ Y,
    int M, int N, int K)
{
    __shared__ float As[16][128 + 4];
    __shared__ float Bs[16][128 + 4];

    const int tid = threadIdx.x;
    const int bm = blockIdx.y * 128;
    const int bn = blockIdx.x * 128;
    const int tm = (tid >> 4) * 8;   // 0..120
    const int tn = (tid & 15) * 8;   // 0..120
    const int lr = tid >> 2;         // 0..63
    const int lc = (tid & 3) << 2;   // 0,4,8,12

    float acc[8][8];
#pragma unroll
    for (int i = 0; i < 8; ++i)
#pragma unroll
        for (int j = 0; j < 8; ++j) acc[i][j] = 0.0f;

    for (int k0 = 0; k0 < K; k0 += 16) {
#pragma unroll
        for (int r = 0; r < 2; ++r) {
            int row = lr + r * 64;
            float4 va = *(const float4*)(X + (size_t)(bm + row) * K + k0 + lc);
            As[lc + 0][row] = va.x; As[lc + 1][row] = va.y;
            As[lc + 2][row] = va.z; As[lc + 3][row] = va.w;
            float4 vb = *(const float4*)(W + (size_t)(bn + row) * K + k0 + lc);
            Bs[lc + 0][row] = vb.x; Bs[lc + 1][row] = vb.y;
            Bs[lc + 2][row] = vb.z; Bs[lc + 3][row] = vb.w;
        }
        __syncthreads();
#pragma unroll
        for (int kk = 0; kk < 16; ++kk) {
            float a[8], b[8];
            *(float4*)&a[0] = *(const float4*)&As[kk][tm];
            *(float4*)&a[4] = *(const float4*)&As[kk][tm + 4];
            *(float4*)&b[0] = *(const float4*)&Bs[kk][tn];
            *(float4*)&b[4] = *(const float4*)&Bs[kk][tn + 4];
#pragma unroll
            for (int i = 0; i < 8; ++i)
#pragma unroll
                for (int j = 0; j < 8; ++j)
                    acc[i][j] = fmaf(a[i], b[j], acc[i][j]);
        }
        __syncthreads();
    }

#pragma unroll
    for (int i = 0; i < 8; ++i) {
        size_t row = (size_t)(bm + tm + i);
#pragma unroll
        for (int j = 0; j < 8; j += 4) {
            float4 o;
            o.x = acc[i][j + 0] + bias[bn + tn + j + 0];
            o.y = acc[i][j + 1] + bias[bn + tn + j + 1];
            o.z = acc[i][j + 2] + bias[bn + tn + j + 2];
            o.w = acc[i][j + 3] + bias[bn + tn + j + 3];
            *(float4*)(Y + row * N + bn + tn + j) = o;
        }
    }
}

// ---------------- attention: two-pass exact softmax + PV + mean_atp ----------
// One block = one (b,h) x 64-query tile. 256 threads (16x16), 4x4 microtiles.
#define BQ 64
#define BKT 64
#define PS_LD (BKT + 4)

// dynamic smem layout (floats):
//   Qs[DK][BQ] | Ks[DK][BKT] | Vs[BKT][DK] | Ps[BQ][PS_LD] | m[BQ] | il[BQ]
#define SMEM_FLOATS (DK*BQ + DK*BKT + BKT*DK + BQ*PS_LD + 2*BQ)

__global__ __launch_bounds__(256) void attn_kernel(float* __restrict__ atp) {
    extern __shared__ float sh[];
    float* Qs   = sh;                       // [DK][BQ]
    float* Ks   = Qs + DK*BQ;               // [DK][BKT]
    float* Vs   = Ks + DK*BKT;              // [BKT][DK]
    float* Ps   = Vs + BKT*DK;              // [BQ][PS_LD]
    float* smm  = Ps + BQ*PS_LD;            // [BQ]
    float* smil = smm + BQ;                 // [BQ]

    const int tid = threadIdx.x;
    const int bh = blockIdx.y;
    const int b = bh / HH, h = bh % HH;
    const int q0 = blockIdx.x * BQ;
    const int ty = tid >> 4;                // 0..15
    const int tx = tid & 15;                // 0..15
    const int tq = ty * 4;
    const int tk = tx * 4;
    const int lr = tid >> 2;                // 0..63 (row for loads)
    const int lc4 = tid & 3;                // float4 group base

    const float* Qg = g_Q + ((size_t)(b * SS + q0)) * DD + h * DK;
    const float* Kg = g_K + ((size_t)b * SS) * DD + h * DK;
    const float* Vg = g_V + ((size_t)b * SS) * DD + h * DK;

    // load Q tile transposed: Qs[d][q]
#pragma unroll
    for (int it = 0; it < 4; ++it) {
        int c4 = lc4 + it * 4;
        float4 v = *(const float4*)(Qg + (size_t)lr * DD + c4 * 4);
        Qs[(c4*4 + 0)*BQ + lr] = v.x; Qs[(c4*4 + 1)*BQ + lr] = v.y;
        Qs[(c4*4 + 2)*BQ + lr] = v.z; Qs[(c4*4 + 3)*BQ + lr] = v.w;
    }

    // -------- sweep 1: per-row max & sumexp (online, then warp-merge) --------
    float m_loc[4], l_loc[4];
#pragma unroll
    for (int i = 0; i < 4; ++i) { m_loc[i] = -INFINITY; l_loc[i] = 0.0f; }

    for (int k0 = 0; k0 < SS; k0 += BKT) {
        __syncthreads();
#pragma unroll
        for (int it = 0; it < 4; ++it) {
            int c4 = lc4 + it * 4;
            float4 v = *(const float4*)(Kg + (size_t)(k0 + lr) * DD + c4 * 4);
            Ks[(c4*4 + 0)*BKT + lr] = v.x; Ks[(c4*4 + 1)*BKT + lr] = v.y;
            Ks[(c4*4 + 2)*BKT + lr] = v.z; Ks[(c4*4 + 3)*BKT + lr] = v.w;
        }
        __syncthreads();

        float s[4][4];
#pragma unroll
        for (int i = 0; i < 4; ++i)
#pragma unroll
            for (int j = 0; j < 4; ++j) s[i][j] = 0.0f;

#pragma unroll
        for (int d = 0; d < DK; ++d) {
            float a[4], bb[4];
            *(float4*)a  = *(const float4*)&Qs[d*BQ + tq];
            *(float4*)bb = *(const float4*)&Ks[d*BKT + tk];
#pragma unroll
            for (int i = 0; i < 4; ++i)
#pragma unroll
                for (int j = 0; j < 4; ++j)
                    s[i][j] = fmaf(a[i], bb[j], s[i][j]);
        }

#pragma unroll
        for (int i = 0; i < 4; ++i) {
            float mt = m_loc[i];
#pragma unroll
            for (int j = 0; j < 4; ++j) {
                s[i][j] *= SCALE;
                mt = fmaxf(mt, s[i][j]);
            }
            if (mt > m_loc[i]) {
                l_loc[i] *= __expf(m_loc[i] - mt);
                m_loc[i] = mt;
            }
#pragma unroll
            for (int j = 0; j < 4; ++j)
                l_loc[i] += __expf(s[i][j] - m_loc[i]);
        }
    }

    // merge across the 16 lanes sharing each query row (tx dimension)
#pragma unroll
    for (int i = 0; i < 4; ++i) {
        float m = m_loc[i], l = l_loc[i];
#pragma unroll
        for (int off = 8; off; off >>= 1) {
            float mo = __shfl_xor_sync(0xffffffffu, m, off);
            float lo = __shfl_xor_sync(0xffffffffu, l, off);
            float mn = fmaxf(m, mo);
            l = l * __expf(m - mn) + lo * __expf(mo - mn);
            m = mn;
        }
        if (tx == 0) { smm[tq + i] = m; smil[tq + i] = 1.0f / l; }
    }
    __syncthreads();

    // -------- sweep 2: exact probs -> atp atomics + PV --------
    float my_m[4], my_il[4];
#pragma unroll
    for (int i = 0; i < 4; ++i) { my_m[i] = smm[tq + i]; my_il[i] = smil[tq + i]; }

    float acc[4][4];
#pragma unroll
    for (int i = 0; i < 4; ++i)
#pragma unroll
        for (int j = 0; j < 4; ++j) acc[i][j] = 0.0f;

    for (int k0 = 0; k0 < SS; k0 += BKT) {
        __syncthreads();
#pragma unroll
        for (int it = 0; it < 4; ++it) {
            int c4 = lc4 + it * 4;
            float4 v = *(const float4*)(Kg + (size_t)(k0 + lr) * DD + c4 * 4);
            Ks[(c4*4 + 0)*BKT + lr] = v.x; Ks[(c4*4 + 1)*BKT + lr] = v.y;
            Ks[(c4*4 + 2)*BKT + lr] = v.z; Ks[(c4*4 + 3)*BKT + lr] = v.w;
            float4 w = *(const float4*)(Vg + (size_t)(k0 + lr) * DD + c4 * 4);
            *(float4*)&Vs[lr*DK + c4*4] = w;
        }
        __syncthreads();

        float s[4][4];
#pragma unroll
        for (int i = 0; i < 4; ++i)
#pragma unroll
            for (int j = 0; j < 4; ++j) s[i][j] = 0.0f;

#pragma unroll
        for (int d = 0; d < DK; ++d) {
            float a[4], bb[4];
            *(float4*)a  = *(const float4*)&Qs[d*BQ + tq];
            *(float4*)bb = *(const float4*)&Ks[d*BKT + tk];
#pragma unroll
            for (int i = 0; i < 4; ++i)
#pragma unroll
                for (int j = 0; j < 4; ++j)
                    s[i][j] = fmaf(a[i], bb[j], s[i][j]);
        }

#pragma unroll
        for (int i = 0; i < 4; ++i) {
            float4 p;
            p.x = __expf(s[i][0] * SCALE - my_m[i]) * my_il[i];
            p.y = __expf(s[i][1] * SCALE - my_m[i]) * my_il[i];
            p.z = __expf(s[i][2] * SCALE - my_m[i]) * my_il[i];
            p.w = __expf(s[i][3] * SCALE - my_m[i]) * my_il[i];
            *(float4*)&Ps[(tq + i)*PS_LD + tk] = p;
        }
        __syncthreads();

        // column sums over q for mean_atp
        {
            int kk = tid >> 2;
            int qs = (tid & 3) * 16;
            float cs = 0.0f;
#pragma unroll
            for (int t = 0; t < 16; ++t) cs += Ps[(qs + t)*PS_LD + kk];
            cs += __shfl_xor_sync(0xffffffffu, cs, 1);
            cs += __shfl_xor_sync(0xffffffffu, cs, 2);
            if ((tid & 3) == 0)
                atomicAdd(&atp[b * SS + k0 + kk], cs * INV_HS);
        }

        // PV: acc[q][d] += P[q][kk] * V[kk][d]
#pragma unroll
        for (int kk = 0; kk < BKT; ++kk) {
            float vb[4];
            *(float4*)vb = *(const float4*)&Vs[kk*DK + tk];
            float pa[4];
#pragma unroll
            for (int i = 0; i < 4; ++i) pa[i] = Ps[(tq + i)*PS_LD + kk];
#pragma unroll
            for (int i = 0; i < 4; ++i)
#pragma unroll
                for (int j = 0; j < 4; ++j)
                    acc[i][j] = fmaf(pa[i], vb[j], acc[i][j]);
        }
    }

    // write context tile: C[b, q0+q, h*DK + d]
    float* Cg = g_C + ((size_t)(b * SS + q0)) * DD + h * DK;
#pragma unroll
    for (int i = 0; i < 4; ++i) {
        float4 o;
        o.x = acc[i][0]; o.y = acc[i][1]; o.z = acc[i][2]; o.w = acc[i][3];
        *(float4*)(Cg + (size_t)(tq + i) * DD + tk) = o;
    }
}

// ---------------- launch ------------------------------------------------------
extern "C" void kernel_launch(void* const* d_in, const int* in_sizes, int n_in,
                              void* d_out, int out_size) {
    (void)in_sizes; (void)n_in; (void)out_size;
    const float* query = (const float*)d_in[0];
    const float* key   = (const float*)d_in[1];
    const float* value = (const float*)d_in[2];
    const float* Wq = (const float*)d_in[3];
    const float* bq = (const float*)d_in[4];
    const float* Wk = (const float*)d_in[5];
    const float* bk = (const float*)d_in[6];
    const float* Wv = (const float*)d_in[7];
    const float* bv = (const float*)d_in[8];
    const float* Wo = (const float*)d_in[9];
    const float* bo = (const float*)d_in[10];

    float* out = (float*)d_out;
    float* atp = out + (size_t)BB * SS * DD;

    float *Qp, *Kp, *Vp, *Cp;
    cudaGetSymbolAddress((void**)&Qp, g_Q);
    cudaGetSymbolAddress((void**)&Kp, g_K);
    cudaGetSymbolAddress((void**)&Vp, g_V);
    cudaGetSymbolAddress((void**)&Cp, g_C);

    zero_atp_kernel<<<(BB*SS + 255) / 256, 256>>>(atp);

    dim3 gg(DD / 128, MTOT / 128);
    sgemm_bias_xwT<<<gg, 256>>>(query, Wq, bq, Qp, MTOT, DD, DD);
    sgemm_bias_xwT<<<gg, 256>>>(key,   Wk, bk, Kp, MTOT, DD, DD);
    sgemm_bias_xwT<<<gg, 256>>>(value, Wv, bv, Vp, MTOT, DD, DD);

    static const size_t smem_bytes = SMEM_FLOATS * sizeof(float);
    cudaFuncSetAttribute(attn_kernel,
                         cudaFuncAttributeMaxDynamicSharedMemorySize,
                         (int)smem_bytes);
    attn_kernel<<<dim3(SS / BQ, BB * HH), 256, smem_bytes>>>(atp);

    sgemm_bias_xwT<<<gg, 256>>>(Cp, Wo, bo, out, MTOT, DD, DD);
}

// round 3
// speedup vs baseline: 1.1143x; 1.1143x over previous
#include <cuda_runtime.h>
#include <math.h>
#include <stdint.h>

#define BB 2
#define SS 2048
#define DD 1024
#define HH 16
#define DK 64
#define MTOT (BB*SS)

#define SCALE 12.5f                  // 100/sqrt(64)
#define INV_HS (1.0f/32768.0f)       // 1/(H*S)

// ---------------- scratch (static device globals; no allocation) -------------
__device__ float g_Q[MTOT*DD];
__device__ float g_K[MTOT*DD];
__device__ float g_V[MTOT*DD];
__device__ float g_C[MTOT*DD];

// ---------------- PTX helpers -------------------------------------------------
__device__ __forceinline__ uint32_t smem_u32(const void* p) {
    uint32_t a;
    asm("{ .reg .u64 t; cvta.to.shared.u64 t, %1; cvt.u32.u64 %0, t; }"
        : "=r"(a) : "l"(p));
    return a;
}

__device__ __forceinline__ uint32_t f32_to_tf32(float x) {
    uint32_t r;
    asm("cvt.rna.tf32.f32 %0, %1;" : "=r"(r) : "f"(x));
    return r;
}

__device__ __forceinline__ void mma_tf32(float c[4],
                                         uint32_t a0, uint32_t a1, uint32_t a2, uint32_t a3,
                                         uint32_t b0, uint32_t b1) {
    asm volatile(
        "mma.sync.aligned.m16n8k8.row.col.f32.tf32.tf32.f32 "
        "{%0,%1,%2,%3}, {%4,%5,%6,%7}, {%8,%9}, {%0,%1,%2,%3};"
        : "+f"(c[0]), "+f"(c[1]), "+f"(c[2]), "+f"(c[3])
        : "r"(a0), "r"(a1), "r"(a2), "r"(a3), "r"(b0), "r"(b1));
}

#define CP_ASYNC16(dst, src) \
    asm volatile("cp.async.cg.shared.global [%0], [%1], 16;" :: "r"(dst), "l"(src))
#define CP_COMMIT() asm volatile("cp.async.commit_group;" ::: "memory")
#define CP_WAIT1()  asm volatile("cp.async.wait_group 1;" ::: "memory")

// ---------------- zero mean_atp region ---------------------------------------
__global__ void zero_atp_kernel(float* __restrict__ atp) {
    int i = blockIdx.x * blockDim.x + threadIdx.x;
    if (i < BB*SS) atp[i] = 0.0f;
}

// ---------------- 3xTF32 mma.sync GEMM: Y[M,1024] = X @ W^T + b ---------------
// BM=BN=128, BK=32, 256 threads (8 warps, 2x4 warp grid), warp tile 64x32.
#define GK 1024
#define GN 1024
#define GBK 32
#define XS_LD 36                      // floats per row (pad 4)
#define TILE_FLOATS (128 * XS_LD)     // 4608
#define GEMM_SMEM (4 * TILE_FLOATS * 4)   // Xs[2] + Ws[2] = 73728 bytes

__global__ __launch_bounds__(256) void gemm_mma(
    const float* __restrict__ X, const float* __restrict__ W,
    const float* __restrict__ bias, float* __restrict__ Y)
{
    extern __shared__ float sh[];
    float* Xs = sh;                       // [2][128][XS_LD]
    float* Ws = sh + 2 * TILE_FLOATS;     // [2][128][XS_LD]

    const int t = threadIdx.x;
    const int w = t >> 5;
    const int lane = t & 31;
    const int g = lane >> 2;              // 0..7
    const int tig = lane & 3;             // 0..3
    const int warp_m = (w >> 2) * 64;     // 0 or 64
    const int warp_n = (w & 3) * 32;      // 0,32,64,96
    const int bm = blockIdx.y * 128;
    const int bn = blockIdx.x * 128;

    // global->shared load mapping: 4 rows of 8x16B per thread
    const int lrow = t >> 3;              // 0..31
    const int lcol = (t & 7) * 4;         // 0..28
    const uint32_t sbX = smem_u32(Xs);
    const uint32_t sbW = smem_u32(Ws);

    float acc[4][4][4];
#pragma unroll
    for (int mi = 0; mi < 4; ++mi)
#pragma unroll
        for (int ni = 0; ni < 4; ++ni)
#pragma unroll
            for (int j = 0; j < 4; ++j) acc[mi][ni][j] = 0.0f;

    const float* Xg = X + (size_t)(bm + lrow) * GK + lcol;
    const float* Wg = W + (size_t)(bn + lrow) * GK + lcol;

    // prologue: stage 0
#pragma unroll
    for (int ir = 0; ir < 4; ++ir) {
        uint32_t dX = sbX + ((lrow + 32 * ir) * XS_LD + lcol) * 4;
        uint32_t dW = sbW + ((lrow + 32 * ir) * XS_LD + lcol) * 4;
        CP_ASYNC16(dX, Xg + (size_t)(32 * ir) * GK);
        CP_ASYNC16(dW, Wg + (size_t)(32 * ir) * GK);
    }
    CP_COMMIT();

    const int NSTAGE = GK / GBK;   // 32
    for (int s = 0; s < NSTAGE; ++s) {
        const int buf = s & 1;
        if (s + 1 < NSTAGE) {
            const int nbuf = (s + 1) & 1;
            const size_t ko = (size_t)(s + 1) * GBK;
#pragma unroll
            for (int ir = 0; ir < 4; ++ir) {
                uint32_t dX = sbX + (nbuf * TILE_FLOATS + (lrow + 32 * ir) * XS_LD + lcol) * 4;
                uint32_t dW = sbW + (nbuf * TILE_FLOATS + (lrow + 32 * ir) * XS_LD + lcol) * 4;
                CP_ASYNC16(dX, Xg + (size_t)(32 * ir) * GK + ko);
                CP_ASYNC16(dW, Wg + (size_t)(32 * ir) * GK + ko);
            }
        }
        CP_COMMIT();
        CP_WAIT1();
        __syncthreads();

        const float* xb = Xs + buf * TILE_FLOATS;
        const float* wb = Ws + buf * TILE_FLOATS;

#pragma unroll
        for (int k8 = 0; k8 < GBK / 8; ++k8) {
            const int k0 = k8 * 8;
            uint32_t AH[4][4], AL[4][4], BH[4][2], BL[4][2];
#pragma unroll
            for (int mi = 0; mi < 4; ++mi) {
                const int r0 = warp_m + mi * 16;
                float v0 = xb[(r0 + g) * XS_LD + k0 + tig];
                float v1 = xb[(r0 + g + 8) * XS_LD + k0 + tig];
                float v2 = xb[(r0 + g) * XS_LD + k0 + tig + 4];
                float v3 = xb[(r0 + g + 8) * XS_LD + k0 + tig + 4];
                AH[mi][0] = f32_to_tf32(v0); AL[mi][0] = f32_to_tf32(v0 - __uint_as_float(AH[mi][0]));
                AH[mi][1] = f32_to_tf32(v1); AL[mi][1] = f32_to_tf32(v1 - __uint_as_float(AH[mi][1]));
                AH[mi][2] = f32_to_tf32(v2); AL[mi][2] = f32_to_tf32(v2 - __uint_as_float(AH[mi][2]));
                AH[mi][3] = f32_to_tf32(v3); AL[mi][3] = f32_to_tf32(v3 - __uint_as_float(AH[mi][3]));
            }
#pragma unroll
            for (int ni = 0; ni < 4; ++ni) {
                const int r0 = warp_n + ni * 8;
                float v0 = wb[(r0 + g) * XS_LD + k0 + tig];
                float v1 = wb[(r0 + g) * XS_LD + k0 + tig + 4];
                BH[ni][0] = f32_to_tf32(v0); BL[ni][0] = f32_to_tf32(v0 - __uint_as_float(BH[ni][0]));
                BH[ni][1] = f32_to_tf32(v1); BL[ni][1] = f32_to_tf32(v1 - __uint_as_float(BH[ni][1]));
            }
#pragma unroll
            for (int mi = 0; mi < 4; ++mi)
#pragma unroll
                for (int ni = 0; ni < 4; ++ni) {
                    mma_tf32(acc[mi][ni], AH[mi][0], AH[mi][1], AH[mi][2], AH[mi][3],
                             BH[ni][0], BH[ni][1]);
                    mma_tf32(acc[mi][ni], AH[mi][0], AH[mi][1], AH[mi][2], AH[mi][3],
                             BL[ni][0], BL[ni][1]);
                    mma_tf32(acc[mi][ni], AL[mi][0], AL[mi][1], AL[mi][2], AL[mi][3],
                             BH[ni][0], BH[ni][1]);
                }
        }
        __syncthreads();
    }

    // epilogue: write with bias
#pragma unroll
    for (int ni = 0; ni < 4; ++ni) {
        const int n = bn + warp_n + ni * 8 + 2 * tig;
        const float2 b2 = *(const float2*)(bias + n);
#pragma unroll
        for (int mi = 0; mi < 4; ++mi) {
            const int r0 = bm + warp_m + mi * 16;
            float2 o0, o1;
            o0.x = acc[mi][ni][0] + b2.x; o0.y = acc[mi][ni][1] + b2.y;
            o1.x = acc[mi][ni][2] + b2.x; o1.y = acc[mi][ni][3] + b2.y;
            *(float2*)(Y + (size_t)(r0 + g) * GN + n)     = o0;
            *(float2*)(Y + (size_t)(r0 + g + 8) * GN + n) = o1;
        }
    }
}

// ---------------- attention: two-pass exact softmax + PV + mean_atp ----------
#define BQ 64
#define BKT 64
#define PS_LD (BKT + 4)
#define SMEM_FLOATS (DK*BQ + DK*BKT + BKT*DK + BQ*PS_LD + 2*BQ)

__global__ __launch_bounds__(256) void attn_kernel(float* __restrict__ atp) {
    extern __shared__ float shf[];
    float* Qs   = shf;
    float* Ks   = Qs + DK*BQ;
    float* Vs   = Ks + DK*BKT;
    float* Ps   = Vs + BKT*DK;
    float* smm  = Ps + BQ*PS_LD;
    float* smil = smm + BQ;

    const int tid = threadIdx.x;
    const int bh = blockIdx.y;
    const int b = bh / HH, h = bh % HH;
    const int q0 = blockIdx.x * BQ;
    const int ty = tid >> 4;
    const int tx = tid & 15;
    const int tq = ty * 4;
    const int tk = tx * 4;
    const int lr = tid >> 2;
    const int lc4 = tid & 3;

    const float* Qg = g_Q + ((size_t)(b * SS + q0)) * DD + h * DK;
    const float* Kg = g_K + ((size_t)b * SS) * DD + h * DK;
    const float* Vg = g_V + ((size_t)b * SS) * DD + h * DK;

#pragma unroll
    for (int it = 0; it < 4; ++it) {
        int c4 = lc4 + it * 4;
        float4 v = *(const float4*)(Qg + (size_t)lr * DD + c4 * 4);
        Qs[(c4*4 + 0)*BQ + lr] = v.x; Qs[(c4*4 + 1)*BQ + lr] = v.y;
        Qs[(c4*4 + 2)*BQ + lr] = v.z; Qs[(c4*4 + 3)*BQ + lr] = v.w;
    }

    float m_loc[4], l_loc[4];
#pragma unroll
    for (int i = 0; i < 4; ++i) { m_loc[i] = -INFINITY; l_loc[i] = 0.0f; }

    for (int k0 = 0; k0 < SS; k0 += BKT) {
        __syncthreads();
#pragma unroll
        for (int it = 0; it < 4; ++it) {
            int c4 = lc4 + it * 4;
            float4 v = *(const float4*)(Kg + (size_t)(k0 + lr) * DD + c4 * 4);
            Ks[(c4*4 + 0)*BKT + lr] = v.x; Ks[(c4*4 + 1)*BKT + lr] = v.y;
            Ks[(c4*4 + 2)*BKT + lr] = v.z; Ks[(c4*4 + 3)*BKT + lr] = v.w;
        }
        __syncthreads();

        float s[4][4];
#pragma unroll
        for (int i = 0; i < 4; ++i)
#pragma unroll
            for (int j = 0; j < 4; ++j) s[i][j] = 0.0f;

#pragma unroll
        for (int d = 0; d < DK; ++d) {
            float a[4], bb[4];
            *(float4*)a  = *(const float4*)&Qs[d*BQ + tq];
            *(float4*)bb = *(const float4*)&Ks[d*BKT + tk];
#pragma unroll
            for (int i = 0; i < 4; ++i)
#pragma unroll
                for (int j = 0; j < 4; ++j)
                    s[i][j] = fmaf(a[i], bb[j], s[i][j]);
        }

#pragma unroll
        for (int i = 0; i < 4; ++i) {
            float mt = m_loc[i];
#pragma unroll
            for (int j = 0; j < 4; ++j) {
                s[i][j] *= SCALE;
                mt = fmaxf(mt, s[i][j]);
            }
            if (mt > m_loc[i]) {
                l_loc[i] *= __expf(m_loc[i] - mt);
                m_loc[i] = mt;
            }
#pragma unroll
            for (int j = 0; j < 4; ++j)
                l_loc[i] += __expf(s[i][j] - m_loc[i]);
        }
    }

#pragma unroll
    for (int i = 0; i < 4; ++i) {
        float m = m_loc[i], l = l_loc[i];
#pragma unroll
        for (int off = 8; off; off >>= 1) {
            float mo = __shfl_xor_sync(0xffffffffu, m, off);
            float lo = __shfl_xor_sync(0xffffffffu, l, off);
            float mn = fmaxf(m, mo);
            l = l * __expf(m - mn) + lo * __expf(mo - mn);
            m = mn;
        }
        if (tx == 0) { smm[tq + i] = m; smil[tq + i] = 1.0f / l; }
    }
    __syncthreads();

    float my_m[4], my_il[4];
#pragma unroll
    for (int i = 0; i < 4; ++i) { my_m[i] = smm[tq + i]; my_il[i] = smil[tq + i]; }

    float acc[4][4];
#pragma unroll
    for (int i = 0; i < 4; ++i)
#pragma unroll
        for (int j = 0; j < 4; ++j) acc[i][j] = 0.0f;

    for (int k0 = 0; k0 < SS; k0 += BKT) {
        __syncthreads();
#pragma unroll
        for (int it = 0; it < 4; ++it) {
            int c4 = lc4 + it * 4;
            float4 v = *(const float4*)(Kg + (size_t)(k0 + lr) * DD + c4 * 4);
            Ks[(c4*4 + 0)*BKT + lr] = v.x; Ks[(c4*4 + 1)*BKT + lr] = v.y;
            Ks[(c4*4 + 2)*BKT + lr] = v.z; Ks[(c4*4 + 3)*BKT + lr] = v.w;
            float4 ww = *(const float4*)(Vg + (size_t)(k0 + lr) * DD + c4 * 4);
            *(float4*)&Vs[lr*DK + c4*4] = ww;
        }
        __syncthreads();

        float s[4][4];
#pragma unroll
        for (int i = 0; i < 4; ++i)
#pragma unroll
            for (int j = 0; j < 4; ++j) s[i][j] = 0.0f;

#pragma unroll
        for (int d = 0; d < DK; ++d) {
            float a[4], bb[4];
            *(float4*)a  = *(const float4*)&Qs[d*BQ + tq];
            *(float4*)bb = *(const float4*)&Ks[d*BKT + tk];
#pragma unroll
            for (int i = 0; i < 4; ++i)
#pragma unroll
                for (int j = 0; j < 4; ++j)
                    s[i][j] = fmaf(a[i], bb[j], s[i][j]);
        }

#pragma unroll
        for (int i = 0; i < 4; ++i) {
            float4 p;
            p.x = __expf(s[i][0] * SCALE - my_m[i]) * my_il[i];
            p.y = __expf(s[i][1] * SCALE - my_m[i]) * my_il[i];
            p.z = __expf(s[i][2] * SCALE - my_m[i]) * my_il[i];
            p.w = __expf(s[i][3] * SCALE - my_m[i]) * my_il[i];
            *(float4*)&Ps[(tq + i)*PS_LD + tk] = p;
        }
        __syncthreads();

        {
            int kk = tid >> 2;
            int qs = (tid & 3) * 16;
            float cs = 0.0f;
#pragma unroll
            for (int tt = 0; tt < 16; ++tt) cs += Ps[(qs + tt)*PS_LD + kk];
            cs += __shfl_xor_sync(0xffffffffu, cs, 1);
            cs += __shfl_xor_sync(0xffffffffu, cs, 2);
            if ((tid & 3) == 0)
                atomicAdd(&atp[b * SS + k0 + kk], cs * INV_HS);
        }

#pragma unroll
        for (int kk = 0; kk < BKT; ++kk) {
            float vb[4];
            *(float4*)vb = *(const float4*)&Vs[kk*DK + tk];
            float pa[4];
#pragma unroll
            for (int i = 0; i < 4; ++i) pa[i] = Ps[(tq + i)*PS_LD + kk];
#pragma unroll
            for (int i = 0; i < 4; ++i)
#pragma unroll
                for (int j = 0; j < 4; ++j)
                    acc[i][j] = fmaf(pa[i], vb[j], acc[i][j]);
        }
    }

    float* Cg = g_C + ((size_t)(b * SS + q0)) * DD + h * DK;
#pragma unroll
    for (int i = 0; i < 4; ++i) {
        float4 o;
        o.x = acc[i][0]; o.y = acc[i][1]; o.z = acc[i][2]; o.w = acc[i][3];
        *(float4*)(Cg + (size_t)(tq + i) * DD + tk) = o;
    }
}

// ---------------- launch ------------------------------------------------------
extern "C" void kernel_launch(void* const* d_in, const int* in_sizes, int n_in,
                              void* d_out, int out_size) {
    (void)in_sizes; (void)n_in; (void)out_size;
    const float* query = (const float*)d_in[0];
    const float* key   = (const float*)d_in[1];
    const float* value = (const float*)d_in[2];
    const float* Wq = (const float*)d_in[3];
    const float* bq = (const float*)d_in[4];
    const float* Wk = (const float*)d_in[5];
    const float* bk = (const float*)d_in[6];
    const float* Wv = (const float*)d_in[7];
    const float* bv = (const float*)d_in[8];
    const float* Wo = (const float*)d_in[9];
    const float* bo = (const float*)d_in[10];

    float* out = (float*)d_out;
    float* atp = out + (size_t)BB * SS * DD;

    float *Qp, *Kp, *Vp, *Cp;
    cudaGetSymbolAddress((void**)&Qp, g_Q);
    cudaGetSymbolAddress((void**)&Kp, g_K);
    cudaGetSymbolAddress((void**)&Vp, g_V);
    cudaGetSymbolAddress((void**)&Cp, g_C);

    zero_atp_kernel<<<(BB*SS + 255) / 256, 256>>>(atp);

    cudaFuncSetAttribute(gemm_mma, cudaFuncAttributeMaxDynamicSharedMemorySize,
                         GEMM_SMEM);

    dim3 gg(GN / 128, MTOT / 128);
    gemm_mma<<<gg, 256, GEMM_SMEM>>>(query, Wq, bq, Qp);
    gemm_mma<<<gg, 256, GEMM_SMEM>>>(key,   Wk, bk, Kp);
    gemm_mma<<<gg, 256, GEMM_SMEM>>>(value, Wv, bv, Vp);

    static const size_t smem_bytes = SMEM_FLOATS * sizeof(float);
    cudaFuncSetAttribute(attn_kernel,
                         cudaFuncAttributeMaxDynamicSharedMemorySize,
                         (int)smem_bytes);
    attn_kernel<<<dim3(SS / BQ, BB * HH), 256, smem_bytes>>>(atp);

    gemm_mma<<<gg, 256, GEMM_SMEM>>>(Cp, Wo, bo, out);
}